// round 14
// baseline (speedup 1.0000x reference)
#include <cuda_runtime.h>
#include <cuda_fp16.h>
#include <math.h>

namespace {
constexpr int B_ = 64, S_ = 512, I_ = 768, H_ = 512, G4 = 2048;
constexpr int BM = 128, BN = 64, BK = 32, NTILE = I_ / BK;
constexpr int GBP_LD = 34;
constexpr int REC_SMEM = 32 * 4 * 32 * 16 + 2 * 64 * GBP_LD * 4;
constexpr int GEMM_SMEM = (2 * 128 * 20 + 2 * 16 * 72) * 4;
constexpr float SC = 256.0f;
constexpr float DSC = 1.0f / 65536.0f;
constexpr unsigned CHUNK_BLOCKS = 64u * 32u;   // blocks per (dir,chunk)
}

__device__ float g_xp[2][(size_t)S_ * B_ * G4];
__device__ uint4 g_A[2][2][8192];
__device__ unsigned g_cnt[2], g_gen2[2];
__device__ unsigned g_ck[8], g_cflag[8];       // per (dir*4+chunk)

__global__ void init_sync_kernel() {
    g_cnt[0] = g_cnt[1] = 0u;
    g_gen2[0] = g_gen2[1] = 0u;
#pragma unroll
    for (int i = 0; i < 8; ++i) { g_ck[i] = 0u; g_cflag[i] = 0u; }
}

__device__ __forceinline__ void hsplit2(float x0, float x1, unsigned& hi, unsigned& lo) {
    __half2 h = __floats2half2_rn(x0, x1);
    const float f0 = __low2float(h), f1 = __high2float(h);
    __half2 l = __floats2half2_rn(x0 - f0, x1 - f1);
    hi = *reinterpret_cast<unsigned*>(&h);
    lo = *reinterpret_cast<unsigned*>(&l);
}
__device__ __forceinline__ void mma_f16(float c[4], const unsigned a[4],
                                        unsigned b0, unsigned b1) {
    asm volatile(
        "mma.sync.aligned.m16n8k16.row.col.f32.f16.f16.f32 "
        "{%0,%1,%2,%3}, {%4,%5,%6,%7}, {%8,%9}, {%0,%1,%2,%3};"
        : "+f"(c[0]), "+f"(c[1]), "+f"(c[2]), "+f"(c[3])
        : "r"(a[0]), "r"(a[1]), "r"(a[2]), "r"(a[3]), "r"(b0), "r"(b1));
}
__device__ __forceinline__ void mma_f16u(float c[4], const uint4& a,
                                         unsigned b0, unsigned b1) {
    asm volatile(
        "mma.sync.aligned.m16n8k16.row.col.f32.f16.f16.f32 "
        "{%0,%1,%2,%3}, {%4,%5,%6,%7}, {%8,%9}, {%0,%1,%2,%3};"
        : "+f"(c[0]), "+f"(c[1]), "+f"(c[2]), "+f"(c[3])
        : "r"(a.x), "r"(a.y), "r"(a.z), "r"(a.w), "r"(b0), "r"(b1));
}

__device__ __forceinline__ unsigned ld_acq(const unsigned* p) {
    unsigned v;
    asm volatile("ld.global.acquire.gpu.u32 %0, [%1];" : "=r"(v) : "l"(p));
    return v;
}
__device__ __forceinline__ void st_rel(unsigned* p, unsigned v) {
    asm volatile("st.global.release.gpu.u32 [%0], %1;" :: "l"(p), "r"(v));
}

// grid (32, 512): y -> priority group pr=y>>6 -> (d, chunk); bb = y&63.
// priority: d0c0, d1c3, d0c1, d1c2, d0c2, d1c1, d0c3, d1c0.
extern "C" __global__ void __launch_bounds__(256, 2)
xproj_gemm(const float* __restrict__ x,
           const float* __restrict__ Wi_f, const float* __restrict__ bi_f,
           const float* __restrict__ bh_f,
           const float* __restrict__ Wi_b, const float* __restrict__ bi_b,
           const float* __restrict__ bh_b) {
    const int pr = blockIdx.y >> 6;
    const int d = pr & 1;
    const int chunk = d ? (3 - (pr >> 1)) : (pr >> 1);
    const int bb = blockIdx.y & 63;
    const int s0 = chunk * 128;
    const float* __restrict__ Wp = d ? Wi_b : Wi_f;
    const float* __restrict__ b1p = d ? bi_b : bi_f;
    const float* __restrict__ b2p = d ? bh_b : bh_f;
    float* __restrict__ xp = g_xp[d];

    extern __shared__ unsigned smg[];
    unsigned* Ah = smg;
    unsigned* Al = Ah + 128 * 20;
    unsigned* Bh = Al + 128 * 20;
    unsigned* Bl = Bh + 16 * 72;

    const int tid = threadIdx.x;
    const int wid = tid >> 5, lane = tid & 31;
    const int wm = wid >> 1, wn = wid & 1;
    const int gid = lane >> 2, tig = lane & 3;
    const int n0 = blockIdx.x * BN;
    const float* Ag = x + ((size_t)bb * S_ + s0) * I_;

    const int ar = tid >> 3, ak = (tid & 7) * 4, aw = (tid & 7) * 2;
    const int bkw = tid & 15, bn0 = (tid >> 4) * 4;

    float acc[2][4][4];
#pragma unroll
    for (int mi = 0; mi < 2; ++mi)
#pragma unroll
        for (int ni = 0; ni < 4; ++ni)
#pragma unroll
            for (int j = 0; j < 4; ++j) acc[mi][ni][j] = 0.f;

    for (int t = 0; t < NTILE; ++t) {
        const int kt = t * BK;
        float4 pa[4];
#pragma unroll
        for (int j = 0; j < 4; ++j)
            pa[j] = *(const float4*)(Ag + (size_t)(ar + 32 * j) * I_ + kt + ak);
        const float4 p0 = *(const float4*)(Wp + (size_t)(kt + 2 * bkw) * G4 + n0 + bn0);
        const float4 p1 = *(const float4*)(Wp + (size_t)(kt + 2 * bkw + 1) * G4 + n0 + bn0);
        __syncthreads();
#pragma unroll
        for (int j = 0; j < 4; ++j) {
            unsigned h0, l0, h1, l1;
            hsplit2(pa[j].x * SC, pa[j].y * SC, h0, l0);
            hsplit2(pa[j].z * SC, pa[j].w * SC, h1, l1);
            const int row = (ar + 32 * j) * 20 + aw;
            *(uint2*)&Ah[row] = make_uint2(h0, h1);
            *(uint2*)&Al[row] = make_uint2(l0, l1);
        }
        {
            uint4 vh, vl;
            hsplit2(p0.x * SC, p1.x * SC, vh.x, vl.x);
            hsplit2(p0.y * SC, p1.y * SC, vh.y, vl.y);
            hsplit2(p0.z * SC, p1.z * SC, vh.z, vl.z);
            hsplit2(p0.w * SC, p1.w * SC, vh.w, vl.w);
            *(uint4*)&Bh[bkw * 72 + bn0] = vh;
            *(uint4*)&Bl[bkw * 72 + bn0] = vl;
        }
        __syncthreads();

#pragma unroll
        for (int ks = 0; ks < 2; ++ks) {
            const int k0w = ks * 8;
            unsigned ahr[2][4], alr[2][4];
#pragma unroll
            for (int mi = 0; mi < 2; ++mi) {
                const int r0 = (wm * 32 + mi * 16 + gid) * 20 + k0w + tig;
                const int r1 = r0 + 8 * 20;
                ahr[mi][0] = Ah[r0]; ahr[mi][1] = Ah[r1];
                ahr[mi][2] = Ah[r0 + 4]; ahr[mi][3] = Ah[r1 + 4];
                alr[mi][0] = Al[r0]; alr[mi][1] = Al[r1];
                alr[mi][2] = Al[r0 + 4]; alr[mi][3] = Al[r1 + 4];
            }
            unsigned bhr[4][2], blr[4][2];
#pragma unroll
            for (int ni = 0; ni < 4; ++ni) {
                const int i0 = (k0w + tig) * 72 + wn * 32 + ni * 8 + gid;
                const int i1 = i0 + 4 * 72;
                bhr[ni][0] = Bh[i0]; bhr[ni][1] = Bh[i1];
                blr[ni][0] = Bl[i0]; blr[ni][1] = Bl[i1];
            }
#pragma unroll
            for (int mi = 0; mi < 2; ++mi)
#pragma unroll
                for (int ni = 0; ni < 4; ++ni) {
                    mma_f16(acc[mi][ni], ahr[mi], bhr[ni][0], bhr[ni][1]);
                    mma_f16(acc[mi][ni], ahr[mi], blr[ni][0], blr[ni][1]);
                    mma_f16(acc[mi][ni], alr[mi], bhr[ni][0], bhr[ni][1]);
                }
        }
    }

#pragma unroll
    for (int mi = 0; mi < 2; ++mi) {
        const int sA = s0 + wm * 32 + mi * 16 + gid;
#pragma unroll
        for (int ni = 0; ni < 4; ++ni) {
            const int gn = n0 + wn * 32 + ni * 8 + 2 * tig;
            const float c0 = b1p[gn] + b2p[gn];
            const float c1 = b1p[gn + 1] + b2p[gn + 1];
            *(float2*)&xp[((size_t)sA * B_ + bb) * G4 + gn] =
                make_float2(fmaf(acc[mi][ni][0], DSC, c0), fmaf(acc[mi][ni][1], DSC, c1));
            *(float2*)&xp[((size_t)(sA + 8) * B_ + bb) * G4 + gn] =
                make_float2(fmaf(acc[mi][ni][2], DSC, c0), fmaf(acc[mi][ni][3], DSC, c1));
        }
    }

    // chunk completion accounting
    __threadfence();
    __syncthreads();
    if (tid == 0) {
        const int ci = d * 4 + chunk;
        const unsigned arr = atomicAdd(&g_ck[ci], 1u) + 1u;
        if (arr == CHUNK_BLOCKS) st_rel(&g_cflag[ci], 1u);
    }
}

__device__ __forceinline__ float sigmf(float x) { return 1.0f / (1.0f + expf(-x)); }

__device__ __forceinline__ void dir_bar(int d, unsigned tgt) {
    __syncthreads();
    if (threadIdx.x == 0) {
        __threadfence();
        unsigned arr = atomicAdd(&g_cnt[d], 1u) + 1u;
        if (arr == 64u * tgt) st_rel(&g_gen2[d], tgt);
        else while (ld_acq(&g_gen2[d]) < tgt) __nanosleep(32);
    }
    __syncthreads();
}

extern "C" __global__ void __launch_bounds__(256, 1)
lstm_recur(const float* __restrict__ sent, float* __restrict__ out,
           const float* __restrict__ Wh_f, const float* __restrict__ Wh_b) {
    const int blk = blockIdx.x, d = blk >> 6, grp = blk & 63, u0 = grp * 8;
    const float* __restrict__ Wh = d ? Wh_b : Wh_f;
    const float* __restrict__ xp = g_xp[d];

    extern __shared__ unsigned smr[];
    uint4* Bs = (uint4*)smr;
    float* gbp = (float*)(Bs + 32 * 4 * 32);

    const int tid = threadIdx.x;
    const int wid = tid >> 5, lane = tid & 31;
    const int gid = lane >> 2, tig = lane & 3;
    const int mt = wid & 3, khw = wid >> 2;

    for (int i = tid; i < 32 * 4 * 32; i += 256) {
        const int ks = i >> 7, nt = (i >> 5) & 3, ln = i & 31;
        const int g = ln >> 2, t2 = ln & 3;
        const int col = nt * H_ + u0 + g;
        const int k0 = ks * 16;
        uint4 v;
        hsplit2(Wh[(size_t)(k0 + 2 * t2) * G4 + col] * SC,
                Wh[(size_t)(k0 + 2 * t2 + 1) * G4 + col] * SC, v.x, v.z);
        hsplit2(Wh[(size_t)(k0 + 8 + 2 * t2) * G4 + col] * SC,
                Wh[(size_t)(k0 + 9 + 2 * t2) * G4 + col] * SC, v.y, v.w);
        Bs[i] = v;
    }
    if (tid < 128) g_A[d][0][grp * 128 + tid] = make_uint4(0u, 0u, 0u, 0u);
    unsigned barno = 1;
    dir_bar(d, barno);

    const int cb = tid >> 2, ue = (tid & 3) * 2;
    const int kstep_p = grp >> 1, half = grp & 1;
    const int mtb = cb >> 4, rh = (cb >> 3) & 1, gb = cb & 7, tb = tid & 3;
    const int pslot = ((kstep_p * 4 + mtb) * 32 + gb * 4 + tb) * 2;
    const float* __restrict__ sent_b = sent + (size_t)cb * S_;
    const int bmark = d ? 127 : 0;
    float cv0 = 0.f, cv1 = 0.f;

    for (int t = 0; t < S_; ++t) {
        const int tt = d ? (S_ - 1 - t) : t;

        // wait for this chunk's input projection (4x per 512 steps)
        if ((tt & 127) == bmark) {
            if (tid == 0) {
                const unsigned* fl = &g_cflag[d * 4 + (tt >> 7)];
                while (ld_acq(fl) == 0u) __nanosleep(64);
            }
            __syncthreads();
        }

        const uint4* __restrict__ Ab = g_A[d][t & 1];
        const int wbuf = 1 - (t & 1);

        const float* xb = xp + ((size_t)tt * B_ + cb) * G4 + u0 + ue;
        const float2 pxi = *(const float2*)(xb);
        const float2 pxf = *(const float2*)(xb + H_);
        const float2 pxg = *(const float2*)(xb + 2 * H_);
        const float2 pxo = *(const float2*)(xb + 3 * H_);
        const float st = sent_b[tt];

        float acc[4][4];
#pragma unroll
        for (int nt = 0; nt < 4; ++nt)
#pragma unroll
            for (int j = 0; j < 4; ++j) acc[nt][j] = 0.f;

        int sl = (((khw * 16) * 4 + mt) * 32 + lane) * 2;
        uint4 nah = __ldcg(&Ab[sl]);
        uint4 nal = __ldcg(&Ab[sl + 1]);
#pragma unroll 4
        for (int ksl = 0; ksl < 16; ++ksl) {
            const uint4 ah = nah, al = nal;
            if (ksl < 15) {
                const int ns = (((khw * 16 + ksl + 1) * 4 + mt) * 32 + lane) * 2;
                nah = __ldcg(&Ab[ns]);
                nal = __ldcg(&Ab[ns + 1]);
            }
            const uint4* bp = &Bs[((khw * 16 + ksl) * 4) * 32 + lane];
#pragma unroll
            for (int nt = 0; nt < 4; ++nt) {
                const uint4 bb2 = bp[nt * 32];
                mma_f16u(acc[nt], ah, bb2.x, bb2.y);
                mma_f16u(acc[nt], ah, bb2.z, bb2.w);
                mma_f16u(acc[nt], al, bb2.x, bb2.y);
            }
        }
        {
            float* gp = gbp + khw * (64 * GBP_LD);
            const int r0 = mt * 16 + gid;
#pragma unroll
            for (int nt = 0; nt < 4; ++nt) {
                *(float2*)&gp[r0 * GBP_LD + nt * 8 + 2 * tig] =
                    make_float2(acc[nt][0], acc[nt][1]);
                *(float2*)&gp[(r0 + 8) * GBP_LD + nt * 8 + 2 * tig] =
                    make_float2(acc[nt][2], acc[nt][3]);
            }
        }
        __syncthreads();

        {
            const float* q0 = gbp + cb * GBP_LD;
            const float* q1 = q0 + 64 * GBP_LD;
            const float2 ia = *(const float2*)(q0 + ue),      ib = *(const float2*)(q1 + ue);
            const float2 fa = *(const float2*)(q0 + 8 + ue),  fb = *(const float2*)(q1 + 8 + ue);
            const float2 ga = *(const float2*)(q0 + 16 + ue), gbv = *(const float2*)(q1 + 16 + ue);
            const float2 oa = *(const float2*)(q0 + 24 + ue), ob = *(const float2*)(q1 + 24 + ue);
            const float xi0 = fmaf(ia.x + ib.x, DSC, pxi.x);
            const float xi1 = fmaf(ia.y + ib.y, DSC, pxi.y);
            const float xf0 = fmaf(fa.x + fb.x, DSC, pxf.x);
            const float xf1 = fmaf(fa.y + fb.y, DSC, pxf.y);
            const float xg0 = fmaf(ga.x + gbv.x, DSC, pxg.x);
            const float xg1 = fmaf(ga.y + gbv.y, DSC, pxg.y);
            const float xo0 = fmaf(oa.x + ob.x, DSC, pxo.x);
            const float xo1 = fmaf(oa.y + ob.y, DSC, pxo.y);
            cv0 = sigmf(xf0) * (1.0f + st) * cv0 + sigmf(xi0) * st * tanhf(xg0);
            cv1 = sigmf(xf1) * (1.0f + st) * cv1 + sigmf(xi1) * st * tanhf(xg1);
            const float hv0 = sigmf(xo0) * tanhf(cv0);
            const float hv1 = sigmf(xo1) * tanhf(cv1);
            *(float2*)&out[((size_t)cb * S_ + tt) * (2 * H_) + d * H_ + u0 + ue] =
                make_float2(hv0, hv1);
            unsigned whi, wlo;
            hsplit2(hv0 * SC, hv1 * SC, whi, wlo);
            unsigned* bas = (unsigned*)&g_A[d][wbuf][pslot];
            bas[half * 2 + rh] = whi;
            bas[4 + half * 2 + rh] = wlo;
        }
        ++barno;
        dir_bar(d, barno);
    }
}

extern "C" void kernel_launch(void* const* d_in, const int* in_sizes, int n_in,
                              void* d_out, int out_size) {
    const float* x    = (const float*)d_in[0];
    const float* sent = (const float*)d_in[1];
    const float* Wi_f = (const float*)d_in[2];
    const float* bi_f = (const float*)d_in[3];
    const float* Wh_f = (const float*)d_in[4];
    const float* bh_f = (const float*)d_in[5];
    const float* Wi_b = (const float*)d_in[6];
    const float* bi_b = (const float*)d_in[7];
    const float* Wh_b = (const float*)d_in[8];
    const float* bh_b = (const float*)d_in[9];
    float* out = (float*)d_out;

    static cudaStream_t s2;
    static cudaEvent_t evA, evB;
    static bool init_done = false;
    if (!init_done) {
        cudaFuncSetAttribute(lstm_recur, cudaFuncAttributeMaxDynamicSharedMemorySize,
                             REC_SMEM);
        cudaFuncSetAttribute(xproj_gemm, cudaFuncAttributeMaxDynamicSharedMemorySize,
                             GEMM_SMEM);
        cudaStreamCreateWithFlags(&s2, cudaStreamNonBlocking);
        cudaEventCreateWithFlags(&evA, cudaEventDisableTiming);
        cudaEventCreateWithFlags(&evB, cudaEventDisableTiming);
        init_done = true;
    }

    init_sync_kernel<<<1, 1>>>();
    // fork: GEMM on s2, recurrence on default stream, concurrent
    cudaEventRecord(evA, 0);
    cudaStreamWaitEvent(s2, evA, 0);
    dim3 ggrid(G4 / BN, 512, 1);
    xproj_gemm<<<ggrid, 256, GEMM_SMEM, s2>>>(x, Wi_f, bi_f, bh_f, Wi_b, bi_b, bh_b);
    lstm_recur<<<128, 256, REC_SMEM>>>(sent, out, Wh_f, Wh_b);
    // join
    cudaEventRecord(evB, s2);
    cudaStreamWaitEvent(0, evB, 0);
}

// round 17
// speedup vs baseline: 1.3253x; 1.3253x over previous
#include <cuda_runtime.h>
#include <cuda_fp16.h>
#include <math.h>

namespace {
constexpr int B_ = 64, S_ = 512, I_ = 768, H_ = 512, G4 = 2048;
constexpr int BM = 128, BN = 64, BK = 32, NTILE = I_ / BK;
constexpr int GBP_LD = 34;
constexpr int REC_SMEM = 32 * 4 * 32 * 16 + 2 * 64 * GBP_LD * 4;
constexpr int GEMM_SMEM = (2 * 128 * 20 + 2 * 16 * 72) * 4;
constexpr float SC = 256.0f;
constexpr float DSC = 1.0f / 65536.0f;
}

__device__ float g_xp[2][(size_t)S_ * B_ * G4];
__device__ uint4 g_A[2][2][8192];
__device__ unsigned g_cnt[2], g_gen2[2];

__global__ void init_sync_kernel() {
    g_cnt[0] = g_cnt[1] = 0u;
    g_gen2[0] = g_gen2[1] = 0u;
}

__device__ __forceinline__ void hsplit2(float x0, float x1, unsigned& hi, unsigned& lo) {
    __half2 h = __floats2half2_rn(x0, x1);
    const float f0 = __low2float(h), f1 = __high2float(h);
    __half2 l = __floats2half2_rn(x0 - f0, x1 - f1);
    hi = *reinterpret_cast<unsigned*>(&h);
    lo = *reinterpret_cast<unsigned*>(&l);
}
__device__ __forceinline__ void mma_f16(float c[4], const unsigned a[4],
                                        unsigned b0, unsigned b1) {
    asm volatile(
        "mma.sync.aligned.m16n8k16.row.col.f32.f16.f16.f32 "
        "{%0,%1,%2,%3}, {%4,%5,%6,%7}, {%8,%9}, {%0,%1,%2,%3};"
        : "+f"(c[0]), "+f"(c[1]), "+f"(c[2]), "+f"(c[3])
        : "r"(a[0]), "r"(a[1]), "r"(a[2]), "r"(a[3]), "r"(b0), "r"(b1));
}
__device__ __forceinline__ void mma_f16u(float c[4], const uint4& a,
                                         unsigned b0, unsigned b1) {
    asm volatile(
        "mma.sync.aligned.m16n8k16.row.col.f32.f16.f16.f32 "
        "{%0,%1,%2,%3}, {%4,%5,%6,%7}, {%8,%9}, {%0,%1,%2,%3};"
        : "+f"(c[0]), "+f"(c[1]), "+f"(c[2]), "+f"(c[3])
        : "r"(a.x), "r"(a.y), "r"(a.z), "r"(a.w), "r"(b0), "r"(b1));
}

// C[(b,s), n] = x @ Wi + bi + bh -> g_xp[d][s][b][n], fp16x2-split (scaled)
extern "C" __global__ void __launch_bounds__(256, 2)
xproj_gemm(const float* __restrict__ x,
           const float* __restrict__ Wi_f, const float* __restrict__ bi_f,
           const float* __restrict__ bh_f,
           const float* __restrict__ Wi_b, const float* __restrict__ bi_b,
           const float* __restrict__ bh_b) {
    const int d = blockIdx.z;
    const float* __restrict__ Wp = d ? Wi_b : Wi_f;
    const float* __restrict__ b1p = d ? bi_b : bi_f;
    const float* __restrict__ b2p = d ? bh_b : bh_f;
    float* __restrict__ xp = g_xp[d];

    extern __shared__ unsigned smg[];
    unsigned* Ah = smg;
    unsigned* Al = Ah + 128 * 20;
    unsigned* Bh = Al + 128 * 20;
    unsigned* Bl = Bh + 16 * 72;

    const int tid = threadIdx.x;
    const int wid = tid >> 5, lane = tid & 31;
    const int wm = wid >> 1, wn = wid & 1;
    const int gid = lane >> 2, tig = lane & 3;
    const int m0 = blockIdx.y * BM, n0 = blockIdx.x * BN;
    const int bb = m0 >> 9, s0 = m0 & 511;
    const float* Ag = x + ((size_t)bb * S_ + s0) * I_;

    const int ar = tid >> 3, ak = (tid & 7) * 4, aw = (tid & 7) * 2;
    const int bkw = tid & 15, bn0 = (tid >> 4) * 4;

    float acc[2][4][4];
#pragma unroll
    for (int mi = 0; mi < 2; ++mi)
#pragma unroll
        for (int ni = 0; ni < 4; ++ni)
#pragma unroll
            for (int j = 0; j < 4; ++j) acc[mi][ni][j] = 0.f;

    for (int t = 0; t < NTILE; ++t) {
        const int kt = t * BK;
        float4 pa[4];
#pragma unroll
        for (int j = 0; j < 4; ++j)
            pa[j] = *(const float4*)(Ag + (size_t)(ar + 32 * j) * I_ + kt + ak);
        const float4 p0 = *(const float4*)(Wp + (size_t)(kt + 2 * bkw) * G4 + n0 + bn0);
        const float4 p1 = *(const float4*)(Wp + (size_t)(kt + 2 * bkw + 1) * G4 + n0 + bn0);
        __syncthreads();
#pragma unroll
        for (int j = 0; j < 4; ++j) {
            unsigned h0, l0, h1, l1;
            hsplit2(pa[j].x * SC, pa[j].y * SC, h0, l0);
            hsplit2(pa[j].z * SC, pa[j].w * SC, h1, l1);
            const int row = (ar + 32 * j) * 20 + aw;
            *(uint2*)&Ah[row] = make_uint2(h0, h1);
            *(uint2*)&Al[row] = make_uint2(l0, l1);
        }
        {
            uint4 vh, vl;
            hsplit2(p0.x * SC, p1.x * SC, vh.x, vl.x);
            hsplit2(p0.y * SC, p1.y * SC, vh.y, vl.y);
            hsplit2(p0.z * SC, p1.z * SC, vh.z, vl.z);
            hsplit2(p0.w * SC, p1.w * SC, vh.w, vl.w);
            *(uint4*)&Bh[bkw * 72 + bn0] = vh;
            *(uint4*)&Bl[bkw * 72 + bn0] = vl;
        }
        __syncthreads();

#pragma unroll
        for (int ks = 0; ks < 2; ++ks) {
            const int k0w = ks * 8;
            unsigned ahr[2][4], alr[2][4];
#pragma unroll
            for (int mi = 0; mi < 2; ++mi) {
                const int r0 = (wm * 32 + mi * 16 + gid) * 20 + k0w + tig;
                const int r1 = r0 + 8 * 20;
                ahr[mi][0] = Ah[r0]; ahr[mi][1] = Ah[r1];
                ahr[mi][2] = Ah[r0 + 4]; ahr[mi][3] = Ah[r1 + 4];
                alr[mi][0] = Al[r0]; alr[mi][1] = Al[r1];
                alr[mi][2] = Al[r0 + 4]; alr[mi][3] = Al[r1 + 4];
            }
            unsigned bhr[4][2], blr[4][2];
#pragma unroll
            for (int ni = 0; ni < 4; ++ni) {
                const int i0 = (k0w + tig) * 72 + wn * 32 + ni * 8 + gid;
                const int i1 = i0 + 4 * 72;
                bhr[ni][0] = Bh[i0]; bhr[ni][1] = Bh[i1];
                blr[ni][0] = Bl[i0]; blr[ni][1] = Bl[i1];
            }
#pragma unroll
            for (int mi = 0; mi < 2; ++mi)
#pragma unroll
                for (int ni = 0; ni < 4; ++ni) {
                    mma_f16(acc[mi][ni], ahr[mi], bhr[ni][0], bhr[ni][1]);
                    mma_f16(acc[mi][ni], ahr[mi], blr[ni][0], blr[ni][1]);
                    mma_f16(acc[mi][ni], alr[mi], bhr[ni][0], bhr[ni][1]);
                }
        }
    }

#pragma unroll
    for (int mi = 0; mi < 2; ++mi) {
        const int sA = s0 + wm * 32 + mi * 16 + gid;
#pragma unroll
        for (int ni = 0; ni < 4; ++ni) {
            const int gn = n0 + wn * 32 + ni * 8 + 2 * tig;
            const float c0 = b1p[gn] + b2p[gn];
            const float c1 = b1p[gn + 1] + b2p[gn + 1];
            *(float2*)&xp[((size_t)sA * B_ + bb) * G4 + gn] =
                make_float2(fmaf(acc[mi][ni][0], DSC, c0), fmaf(acc[mi][ni][1], DSC, c1));
            *(float2*)&xp[((size_t)(sA + 8) * B_ + bb) * G4 + gn] =
                make_float2(fmaf(acc[mi][ni][2], DSC, c0), fmaf(acc[mi][ni][3], DSC, c1));
        }
    }
}

__device__ __forceinline__ float sigmf(float x) { return 1.0f / (1.0f + expf(-x)); }

__device__ __forceinline__ unsigned ld_acq(const unsigned* p) {
    unsigned v;
    asm volatile("ld.global.acquire.gpu.u32 %0, [%1];" : "=r"(v) : "l"(p));
    return v;
}
__device__ __forceinline__ void st_rel(unsigned* p, unsigned v) {
    asm volatile("st.global.release.gpu.u32 [%0], %1;" :: "l"(p), "r"(v));
}
__device__ __forceinline__ void dir_bar(int d, unsigned tgt) {
    __syncthreads();
    if (threadIdx.x == 0) {
        __threadfence();
        unsigned arr = atomicAdd(&g_cnt[d], 1u) + 1u;
        if (arr == 64u * tgt) st_rel(&g_gen2[d], tgt);
        else while (ld_acq(&g_gen2[d]) < tgt) __nanosleep(32);
    }
    __syncthreads();
}

// 128 persistent blocks, 256 threads; dir = blk>>6; block owns 8 hidden units
// (32 gate cols). C[64x32] = h[64x512] @ Whslice per step, fp16x2-split MMA.
// A-fragment loads software-pipelined at depth 4 to hide L2 latency.
extern "C" __global__ void __launch_bounds__(256, 1)
lstm_recur(const float* __restrict__ sent, float* __restrict__ out,
           const float* __restrict__ Wh_f, const float* __restrict__ Wh_b) {
    const int blk = blockIdx.x, d = blk >> 6, grp = blk & 63, u0 = grp * 8;
    const float* __restrict__ Wh = d ? Wh_b : Wh_f;
    const float* __restrict__ xp = g_xp[d];

    extern __shared__ unsigned smr[];
    uint4* Bs = (uint4*)smr;                    // [32 ks][4 nt][32 lane]
    float* gbp = (float*)(Bs + 32 * 4 * 32);    // [2][64][GBP_LD]

    const int tid = threadIdx.x;
    const int wid = tid >> 5, lane = tid & 31;
    const int gid = lane >> 2, tig = lane & 3;
    const int mt = wid & 3, khw = wid >> 2;

    for (int i = tid; i < 32 * 4 * 32; i += 256) {
        const int ks = i >> 7, nt = (i >> 5) & 3, ln = i & 31;
        const int g = ln >> 2, t2 = ln & 3;
        const int col = nt * H_ + u0 + g;
        const int k0 = ks * 16;
        uint4 v;
        hsplit2(Wh[(size_t)(k0 + 2 * t2) * G4 + col] * SC,
                Wh[(size_t)(k0 + 2 * t2 + 1) * G4 + col] * SC, v.x, v.z);
        hsplit2(Wh[(size_t)(k0 + 8 + 2 * t2) * G4 + col] * SC,
                Wh[(size_t)(k0 + 9 + 2 * t2) * G4 + col] * SC, v.y, v.w);
        Bs[i] = v;
    }
    if (tid < 128) g_A[d][0][grp * 128 + tid] = make_uint4(0u, 0u, 0u, 0u);
    unsigned barno = 1;
    dir_bar(d, barno);

    const int cb = tid >> 2, ue = (tid & 3) * 2;
    const int kstep_p = grp >> 1, half = grp & 1;
    const int mtb = cb >> 4, rh = (cb >> 3) & 1, gb = cb & 7, tb = tid & 3;
    const int pslot = ((kstep_p * 4 + mtb) * 32 + gb * 4 + tb) * 2;
    const float* __restrict__ sent_b = sent + (size_t)cb * S_;
    const int abase = (((khw * 16) * 4 + mt) * 32 + lane) * 2;  // uint4 index, +256/ksl
    float cv0 = 0.f, cv1 = 0.f;

    for (int t = 0; t < S_; ++t) {
        const int tt = d ? (S_ - 1 - t) : t;
        const uint4* __restrict__ Ap = g_A[d][t & 1] + abase;
        const int wbuf = 1 - (t & 1);

        const float* xb = xp + ((size_t)tt * B_ + cb) * G4 + u0 + ue;
        const float2 pxi = *(const float2*)(xb);
        const float2 pxf = *(const float2*)(xb + H_);
        const float2 pxg = *(const float2*)(xb + 2 * H_);
        const float2 pxo = *(const float2*)(xb + 3 * H_);
        const float st = sent_b[tt];

        float acc[4][4];
#pragma unroll
        for (int nt = 0; nt < 4; ++nt)
#pragma unroll
            for (int j = 0; j < 4; ++j) acc[nt][j] = 0.f;

        // depth-4 software pipeline on A fragments
        uint4 bh4[4], bl4[4];
#pragma unroll
        for (int p = 0; p < 4; ++p) {
            bh4[p] = __ldcg(Ap + p * 256);
            bl4[p] = __ldcg(Ap + p * 256 + 1);
        }
#pragma unroll
        for (int ksl = 0; ksl < 16; ++ksl) {
            const uint4 ah = bh4[ksl & 3], al = bl4[ksl & 3];
            if (ksl < 12) {
                bh4[ksl & 3] = __ldcg(Ap + (ksl + 4) * 256);
                bl4[ksl & 3] = __ldcg(Ap + (ksl + 4) * 256 + 1);
            }
            const uint4* bp = &Bs[((khw * 16 + ksl) * 4) * 32 + lane];
#pragma unroll
            for (int nt = 0; nt < 4; ++nt) {
                const uint4 bb2 = bp[nt * 32];
                mma_f16u(acc[nt], ah, bb2.x, bb2.y);
                mma_f16u(acc[nt], ah, bb2.z, bb2.w);
                mma_f16u(acc[nt], al, bb2.x, bb2.y);
            }
        }
        {
            float* gp = gbp + khw * (64 * GBP_LD);
            const int r0 = mt * 16 + gid;
#pragma unroll
            for (int nt = 0; nt < 4; ++nt) {
                *(float2*)&gp[r0 * GBP_LD + nt * 8 + 2 * tig] =
                    make_float2(acc[nt][0], acc[nt][1]);
                *(float2*)&gp[(r0 + 8) * GBP_LD + nt * 8 + 2 * tig] =
                    make_float2(acc[nt][2], acc[nt][3]);
            }
        }
        __syncthreads();

        {
            const float* q0 = gbp + cb * GBP_LD;
            const float* q1 = q0 + 64 * GBP_LD;
            const float2 ia = *(const float2*)(q0 + ue),      ib = *(const float2*)(q1 + ue);
            const float2 fa = *(const float2*)(q0 + 8 + ue),  fb = *(const float2*)(q1 + 8 + ue);
            const float2 ga = *(const float2*)(q0 + 16 + ue), gbv = *(const float2*)(q1 + 16 + ue);
            const float2 oa = *(const float2*)(q0 + 24 + ue), ob = *(const float2*)(q1 + 24 + ue);
            const float xi0 = fmaf(ia.x + ib.x, DSC, pxi.x);
            const float xi1 = fmaf(ia.y + ib.y, DSC, pxi.y);
            const float xf0 = fmaf(fa.x + fb.x, DSC, pxf.x);
            const float xf1 = fmaf(fa.y + fb.y, DSC, pxf.y);
            const float xg0 = fmaf(ga.x + gbv.x, DSC, pxg.x);
            const float xg1 = fmaf(ga.y + gbv.y, DSC, pxg.y);
            const float xo0 = fmaf(oa.x + ob.x, DSC, pxo.x);
            const float xo1 = fmaf(oa.y + ob.y, DSC, pxo.y);
            cv0 = sigmf(xf0) * (1.0f + st) * cv0 + sigmf(xi0) * st * tanhf(xg0);
            cv1 = sigmf(xf1) * (1.0f + st) * cv1 + sigmf(xi1) * st * tanhf(xg1);
            const float hv0 = sigmf(xo0) * tanhf(cv0);
            const float hv1 = sigmf(xo1) * tanhf(cv1);
            *(float2*)&out[((size_t)cb * S_ + tt) * (2 * H_) + d * H_ + u0 + ue] =
                make_float2(hv0, hv1);
            unsigned whi, wlo;
            hsplit2(hv0 * SC, hv1 * SC, whi, wlo);
            unsigned* bas = (unsigned*)&g_A[d][wbuf][pslot];
            bas[half * 2 + rh] = whi;
            bas[4 + half * 2 + rh] = wlo;
        }
        ++barno;
        dir_bar(d, barno);
    }
}

extern "C" void kernel_launch(void* const* d_in, const int* in_sizes, int n_in,
                              void* d_out, int out_size) {
    const float* x    = (const float*)d_in[0];
    const float* sent = (const float*)d_in[1];
    const float* Wi_f = (const float*)d_in[2];
    const float* bi_f = (const float*)d_in[3];
    const float* Wh_f = (const float*)d_in[4];
    const float* bh_f = (const float*)d_in[5];
    const float* Wi_b = (const float*)d_in[6];
    const float* bi_b = (const float*)d_in[7];
    const float* Wh_b = (const float*)d_in[8];
    const float* bh_b = (const float*)d_in[9];
    float* out = (float*)d_out;

    static bool attr_done = false;
    if (!attr_done) {
        cudaFuncSetAttribute(lstm_recur, cudaFuncAttributeMaxDynamicSharedMemorySize,
                             REC_SMEM);
        cudaFuncSetAttribute(xproj_gemm, cudaFuncAttributeMaxDynamicSharedMemorySize,
                             GEMM_SMEM);
        attr_done = true;
    }

    dim3 ggrid(G4 / BN, (B_ * S_) / BM, 2);
    xproj_gemm<<<ggrid, 256, GEMM_SMEM>>>(x, Wi_f, bi_f, bh_f, Wi_b, bi_b, bh_b);
    init_sync_kernel<<<1, 1>>>();
    lstm_recur<<<128, 256, REC_SMEM>>>(sent, out, Wh_f, Wh_b);
}